// round 10
// baseline (speedup 1.0000x reference)
#include <cuda_runtime.h>
#include <cuda_fp16.h>
#include <cstdint>

#define HIDDEN 1024
#define NHEADS 16
#define HDIM 64
#define BATCH 2
#define SEQ 2048
#define SCALE 0.03125f  /* HIDDEN^-0.5 */
#define L2E 1.4426950408889634f

// scratch (allocation-free rule: __device__ globals) — all fp16
__device__ __half g_q[BATCH * NHEADS * SEQ * HDIM];
__device__ __half g_k[BATCH * NHEADS * SEQ * HDIM];
__device__ __half g_vt[BATCH * NHEADS * HDIM * SEQ];  // V TRANSPOSED: [bh][d][n]
__device__ __half g_hid[BATCH * SEQ * HIDDEN];        // fp16 hidden
__device__ __half g_wt[NHEADS * 192 * HIDDEN];        // fp16 W, TRANSPOSED [h][col][k]

__device__ __forceinline__ unsigned packh2(float a, float b) {
    __half2 h = __floats2half2_rn(a, b);
    return *(unsigned*)&h;
}

// D += A*B, m16n8k16, fp16 inputs, fp32 accumulate
__device__ __forceinline__ void mma_f16(float c[4], const unsigned a[4], const unsigned b[2]) {
    asm volatile(
        "mma.sync.aligned.m16n8k16.row.col.f32.f16.f16.f32 "
        "{%0,%1,%2,%3},{%4,%5,%6,%7},{%8,%9},{%0,%1,%2,%3};\n"
        : "+f"(c[0]), "+f"(c[1]), "+f"(c[2]), "+f"(c[3])
        : "r"(a[0]), "r"(a[1]), "r"(a[2]), "r"(a[3]), "r"(b[0]), "r"(b[1]));
}

__device__ __forceinline__ void ldsm4(unsigned& r0, unsigned& r1, unsigned& r2,
                                      unsigned& r3, unsigned addr) {
    asm volatile("ldmatrix.sync.aligned.m8n8.x4.shared.b16 {%0,%1,%2,%3}, [%4];"
                 : "=r"(r0), "=r"(r1), "=r"(r2), "=r"(r3) : "r"(addr));
}

__device__ __forceinline__ void cp_async16(unsigned dst, const void* src) {
    asm volatile("cp.async.cg.shared.global [%0], [%1], 16;\n" :: "r"(dst), "l"(src));
}
__device__ __forceinline__ void cp_commit() { asm volatile("cp.async.commit_group;\n"); }
__device__ __forceinline__ void cp_wait0() { asm volatile("cp.async.wait_group 0;\n"); }

// ---------------------------------------------------------------------------
// Kernel 0a: fp32 -> fp16 (hidden).
// ---------------------------------------------------------------------------
__global__ __launch_bounds__(256) void cvt_kernel(const float* __restrict__ src,
                                                  __half* __restrict__ dst, int n4) {
    int i = blockIdx.x * blockDim.x + threadIdx.x;
    int stride = gridDim.x * blockDim.x;
    for (; i < n4; i += stride) {
        float4 v = ((const float4*)src)[i];
        uint2 u;
        u.x = packh2(v.x, v.y);
        u.y = packh2(v.z, v.w);
        ((uint2*)dst)[i] = u;
    }
}

// ---------------------------------------------------------------------------
// Kernel 0b: fp32 W [h][k][c] -> fp16 TRANSPOSED [h][c][k]. 32x32 tiles.
// ---------------------------------------------------------------------------
__global__ __launch_bounds__(256) void cvtT_kernel(const float* __restrict__ W,
                                                   __half* __restrict__ Wt) {
    __shared__ float t[32][33];
    const int h = blockIdx.z, c0 = blockIdx.x * 32, k0 = blockIdx.y * 32;
    const int tx = threadIdx.x & 31, ty = threadIdx.x >> 5;
    const float* Wh = W + (size_t)h * HIDDEN * 192;
    __half* Wth = Wt + (size_t)h * 192 * HIDDEN;
#pragma unroll
    for (int i = 0; i < 4; i++) {
        int r = ty + 8 * i;
        t[r][tx] = Wh[(size_t)(k0 + r) * 192 + c0 + tx];
    }
    __syncthreads();
#pragma unroll
    for (int i = 0; i < 4; i++) {
        int r = ty + 8 * i;
        Wth[(size_t)(c0 + r) * HIDDEN + k0 + tx] = __float2half(t[tx][r]);
    }
}

// ---------------------------------------------------------------------------
// Kernel 1: fused QKV projection (fp16 m16n8k16, all-LDSM), flattened cols.
// C[4096, 3072] = hidden x Wall. BM=128, BN=128, BK=64, 256 thr / 8 warps.
// Epilogue now STAGES C through smem -> fully coalesced 16B global stores
// (was: scattered 2-4B stores with 8-16x sector amplification).
// smem halves: A[2][128*72] @0, B[2][128*72] @18432 = 36864 (73728 B).
// Epilogue reuses the same smem as a 128x136 fp16 C tile (34816 B).
// ---------------------------------------------------------------------------
#define QSTR 72
#define QAW 9216
#define QB_BASE 18432
#define QBW 9216
#define QKV_SMEM_BYTES 73728
#define CSTR 136

__global__ __launch_bounds__(256, 2) void qkv_kernel(const __half* __restrict__ hidden,
                                                     const __half* __restrict__ Wt) {
    extern __shared__ __half qsh[];
    const unsigned smb = (unsigned)__cvta_generic_to_shared(qsh);

    const int n0  = blockIdx.x * 128;       // flattened col base (0..3071)
    const int m0  = blockIdx.y * 128;
    const int tid = threadIdx.x;
    const int wid = tid >> 5, lane = tid & 31;
    const int g   = lane >> 2, tg = lane & 3;
    const int wy  = wid & 3;     // m: wy*32
    const int wx  = wid >> 2;    // n: wx*64

    const int rA = (lane & 7) + (((lane >> 3) & 1) << 3);
    const int kA = (lane >> 4) * 8;
    const unsigned lmA = (unsigned)((rA * QSTR + kA) * 2);
    const int rB = (lane & 7) + ((lane >> 4) << 3);
    const int kB = ((lane >> 3) & 1) * 8;
    const unsigned lmB = (unsigned)((rB * QSTR + kB) * 2);

    const int pr = tid >> 1;
    const int pc = (tid & 1) * 32;
    const int gc = n0 + pr;
    const __half* wrow = Wt + (size_t)(gc / 192) * (192 * HIDDEN) + (size_t)(gc % 192) * HIDDEN;
    const __half* arow = hidden + (size_t)(m0 + pr) * HIDDEN;

#define QKV_PREF(buf, k0)                                                        \
    {                                                                             \
        _Pragma("unroll")                                                         \
        for (int j = 0; j < 4; j++) {                                             \
            cp_async16(smb + (unsigned)(((buf) * QAW + pr * QSTR + pc + 8 * j) * 2), \
                       arow + (k0) + pc + 8 * j);                                 \
            cp_async16(smb + (unsigned)((QB_BASE + (buf) * QBW + pr * QSTR + pc + 8 * j) * 2), \
                       wrow + (k0) + pc + 8 * j);                                 \
        }                                                                         \
    }

    QKV_PREF(0, 0);
    cp_commit();

    float acc[2][8][4] = {};

    for (int kt = 0; kt < HIDDEN / 64; kt++) {
        const int c = kt & 1;
        cp_wait0();
        __syncthreads();
        if (kt + 1 < HIDDEN / 64) { QKV_PREF(c ^ 1, (kt + 1) * 64); cp_commit(); }

        const unsigned aB = smb + (unsigned)(c * QAW * 2) + lmA;
        const unsigned bB = smb + (unsigned)((QB_BASE + c * QBW) * 2) + lmB;

#pragma unroll
        for (int ks = 0; ks < 4; ks++) {
            const int kk = ks * 16;
            unsigned af[2][4];
#pragma unroll
            for (int mt = 0; mt < 2; mt++)
                ldsm4(af[mt][0], af[mt][1], af[mt][2], af[mt][3],
                      aB + (unsigned)(((wy * 32 + mt * 16) * QSTR + kk) * 2));
#pragma unroll
            for (int ntp = 0; ntp < 4; ntp++) {
                unsigned b0, b1, b2, b3;
                ldsm4(b0, b1, b2, b3, bB + (unsigned)(((wx * 64 + ntp * 16) * QSTR + kk) * 2));
                unsigned bfa[2] = {b0, b1}, bfb[2] = {b2, b3};
#pragma unroll
                for (int mt = 0; mt < 2; mt++) {
                    mma_f16(acc[mt][2 * ntp],     af[mt], bfa);
                    mma_f16(acc[mt][2 * ntp + 1], af[mt], bfb);
                }
            }
        }
    }

    // ---- epilogue: stage C (128x128 fp16) in smem, then coalesced stores ----
    __syncthreads();   // all fragment reads done; smem reusable
#pragma unroll
    for (int mt = 0; mt < 2; mt++) {
        const int row = wy * 32 + mt * 16 + g;
#pragma unroll
        for (int nt = 0; nt < 8; nt++) {
            const int coln = wx * 64 + nt * 8 + 2 * tg;
            *(unsigned*)&qsh[row * CSTR + coln]       = packh2(acc[mt][nt][0], acc[mt][nt][1]);
            *(unsigned*)&qsh[(row + 8) * CSTR + coln] = packh2(acc[mt][nt][2], acc[mt][nt][3]);
        }
    }
    __syncthreads();

    const int b = m0 >> 11;            // whole block in one batch (128 | 2048)
    const int nbase = m0 & 2047;
#pragma unroll
    for (int gi = 0; gi < 2; gi++) {   // two 64-col groups; each maps to one (head, q/k/vt)
        const int gcol = n0 + 64 * gi;
        const int head = gcol / 192;
        const int hc = gcol % 192;
        const int sel = hc >> 6;
        if (sel != 2) {
            __half* dst = (sel == 0) ? g_q : g_k;
            const int r = tid >> 1, ho = (tid & 1) * 32;
            const size_t gbase = (((size_t)(b * NHEADS + head)) * SEQ + nbase + r) * HDIM + ho;
#pragma unroll
            for (int j = 0; j < 4; j++)
                *(uint4*)&dst[gbase + 8 * j] = *(uint4*)&qsh[r * CSTR + 64 * gi + ho + 8 * j];
        } else {
            const int d = tid >> 2, nq = (tid & 3) * 32;
            const size_t gbase = ((size_t)(b * NHEADS + head) * HDIM + d) * SEQ + nbase + nq;
#pragma unroll
            for (int j = 0; j < 4; j++) {
                __half tmp[8];
#pragma unroll
                for (int u = 0; u < 8; u++)
                    tmp[u] = qsh[(nq + 8 * j + u) * CSTR + 64 * gi + d];
                *(uint4*)&g_vt[gbase + 8 * j] = *(uint4*)tmp;
            }
        }
    }
}

// ---------------------------------------------------------------------------
// Kernel 2: flash attention (fp16 m16n8k16). BQ=64, BKV=64, 128 thr / 4 warps,
// 4 blocks/SM -> 4 independent softmax chains overlap LDSM with HMMA.
// smem halves: K[2][64*72] @0, Vt[2][64*72] @9216; flags(int)[2][64] @36864B.
// ---------------------------------------------------------------------------
#define FSTR 72
#define FVBASE 9216
#define FLI 9216          /* int index of flags (byte 36864) */
#define FLASH_SMEM_BYTES 37376

__global__ __launch_bounds__(128, 4) void flash_kernel(const int* __restrict__ mask,
                                                       float* __restrict__ out) {
    extern __shared__ __half smh[];
    int* smi = (int*)smh;
    const unsigned smbase = (unsigned)__cvta_generic_to_shared(smh);

    const int bh = blockIdx.y, b = bh >> 4, h = bh & 15;
    const int q0 = blockIdx.x * 64;
    const int tid = threadIdx.x, wid = tid >> 5, lane = tid & 31;
    const int g = lane >> 2, tg = lane & 3;
    const int row0 = wid * 16 + g, row1 = row0 + 8;

    const __half* Qg  = g_q + (size_t)bh * SEQ * HDIM;
    const __half* Kg  = g_k + (size_t)bh * SEQ * HDIM;
    const __half* Vtg = g_vt + (size_t)bh * HDIM * SEQ;
    const int* maskb = mask + b * SEQ;

    const int rA = (lane & 7) + (((lane >> 3) & 1) << 3);
    const int kA = (lane >> 4) * 8;
    const unsigned lmA = (unsigned)((rA * FSTR + kA) * 2);
    const int rB = (lane & 7) + ((lane >> 4) << 3);
    const int kB = ((lane >> 3) & 1) * 8;
    const unsigned lmB = (unsigned)((rB * FSTR + kB) * 2);

    // ---- stage Q (x SCALE) as fp16 into smem (64 rows), pull A-frags ----
    {
        const __half2 hs = __float2half2_rn(SCALE);
        const int lr = tid >> 1;
        const int lgp = (tid & 1) * 8;
        const uint2* qrow = (const uint2*)&Qg[(size_t)(q0 + lr) * HDIM];
#pragma unroll
        for (int j = 0; j < 8; j++) {
            uint2 u = qrow[lgp + j];
            __half2* hp = (__half2*)&u;
            hp[0] = __hmul2(hp[0], hs);
            hp[1] = __hmul2(hp[1], hs);
            *(uint2*)&smh[lr * FSTR + (lgp + j) * 4] = u;
        }
    }
    __syncthreads();
    unsigned qa[4][4];
#pragma unroll
    for (int kc = 0; kc < 4; kc++)
        ldsm4(qa[kc][0], qa[kc][1], qa[kc][2], qa[kc][3],
              smbase + (unsigned)((wid * 16 * FSTR + kc * 16) * 2) + lmA);
    __syncthreads();

    // prefetch: 128 threads, K 64x64 halves -> 4 chunks/thread; V same
    const int kr = tid >> 1;
    const int kc2 = (tid & 1) * 32;
#define PREFETCH(buf, j0)                                                         \
    {                                                                             \
        _Pragma("unroll")                                                         \
        for (int j = 0; j < 4; j++) {                                             \
            cp_async16(smbase + (unsigned)(((buf) * 4608 + kr * FSTR + kc2 + 8 * j) * 2), \
                       &Kg[(size_t)((j0) + kr) * HDIM + kc2 + 8 * j]);            \
            cp_async16(smbase + (unsigned)((FVBASE + (buf) * 4608 + kr * FSTR + kc2 + 8 * j) * 2), \
                       &Vtg[(size_t)kr * SEQ + (j0) + kc2 + 8 * j]);              \
        }                                                                         \
        if (tid < 16)                                                             \
            cp_async16(smbase + (unsigned)(36864 + (buf) * 256 + tid * 16),       \
                       &maskb[(j0) + tid * 4]);                                   \
    }

    PREFETCH(0, 0);
    cp_commit();

    float l0r = 0.f, l1r = 0.f;
    float o[8][4] = {};
    float s[8][4];

    for (int it = 0; it < 32; ++it) {
        const int c = it & 1;
        const unsigned kbB = smbase + (unsigned)(c * 4608 * 2) + lmB;
        const unsigned vbB = smbase + (unsigned)((FVBASE + c * 4608) * 2) + lmB;

        cp_wait0();
        __syncthreads();
        if (it + 1 < 32) { PREFETCH(c ^ 1, (it + 1) * 64); cp_commit(); }

        // ---- S = Q K^T ----
#pragma unroll
        for (int nt = 0; nt < 8; nt++) { s[nt][0] = 0.f; s[nt][1] = 0.f; s[nt][2] = 0.f; s[nt][3] = 0.f; }
#pragma unroll
        for (int kc = 0; kc < 4; kc++) {
            const int kk = kc * 16;
#pragma unroll
            for (int ntp = 0; ntp < 4; ntp++) {
                unsigned b0, b1, b2, b3;
                ldsm4(b0, b1, b2, b3, kbB + (unsigned)((ntp * 16 * FSTR + kk) * 2));
                unsigned bfa[2] = {b0, b1}, bfb[2] = {b2, b3};
                mma_f16(s[2 * ntp],     qa[kc], bfa);
                mma_f16(s[2 * ntp + 1], qa[kc], bfb);
            }
        }

        // ---- mask + P = 2^(s*log2e) via f16x2 MUFU; fp32 row sums ----
        unsigned p01[8], p23[8];
        float ps0 = 0.f, ps1 = 0.f;
#pragma unroll
        for (int nt = 0; nt < 8; nt++) {
            const int cb = nt * 8 + 2 * tg;
            if (smi[FLI + c * 64 + cb] == 0)     { s[nt][0] = -1e4f; s[nt][2] = -1e4f; }
            if (smi[FLI + c * 64 + cb + 1] == 0) { s[nt][1] = -1e4f; s[nt][3] = -1e4f; }
            unsigned a01 = packh2(s[nt][0] * L2E, s[nt][1] * L2E);
            unsigned a23 = packh2(s[nt][2] * L2E, s[nt][3] * L2E);
            asm("ex2.approx.f16x2 %0, %0;" : "+r"(a01));
            asm("ex2.approx.f16x2 %0, %0;" : "+r"(a23));
            p01[nt] = a01; p23[nt] = a23;
            float2 f0 = __half22float2(*(__half2*)&a01);
            float2 f1 = __half22float2(*(__half2*)&a23);
            ps0 += f0.x + f0.y;
            ps1 += f1.x + f1.y;
        }
        ps0 += __shfl_xor_sync(0xffffffffu, ps0, 1);
        ps0 += __shfl_xor_sync(0xffffffffu, ps0, 2);
        ps1 += __shfl_xor_sync(0xffffffffu, ps1, 1);
        ps1 += __shfl_xor_sync(0xffffffffu, ps1, 2);
        l0r += ps0;
        l1r += ps1;

        // ---- O += P V : P A-frags are the ex2 outputs directly ----
#pragma unroll
        for (int kc = 0; kc < 4; kc++) {
            unsigned ap[4];
            ap[0] = p01[2 * kc];     ap[1] = p23[2 * kc];
            ap[2] = p01[2 * kc + 1]; ap[3] = p23[2 * kc + 1];
#pragma unroll
            for (int ntp = 0; ntp < 4; ntp++) {
                unsigned b0, b1, b2, b3;
                ldsm4(b0, b1, b2, b3, vbB + (unsigned)((ntp * 16 * FSTR + kc * 16) * 2));
                unsigned bfa[2] = {b0, b1}, bfb[2] = {b2, b3};
                mma_f16(o[2 * ntp],     ap, bfa);
                mma_f16(o[2 * ntp + 1], ap, bfb);
            }
        }
    }

    const float inv0 = 1.f / l0r, inv1 = 1.f / l1r;
#pragma unroll
    for (int nt = 0; nt < 8; nt++) {
        const int col = h * HDIM + nt * 8 + 2 * tg;
        const size_t o0 = ((size_t)(b * SEQ + q0 + row0)) * HIDDEN + col;
        const size_t o1 = ((size_t)(b * SEQ + q0 + row1)) * HIDDEN + col;
        *(float2*)&out[o0] = make_float2(o[nt][0] * inv0, o[nt][1] * inv0);
        *(float2*)&out[o1] = make_float2(o[nt][2] * inv1, o[nt][3] * inv1);
    }
}

// ---------------------------------------------------------------------------
extern "C" void kernel_launch(void* const* d_in, const int* in_sizes, int n_in,
                              void* d_out, int out_size) {
    const float* hidden = (const float*)d_in[0];   // [2, 2048, 1024] f32
    const int*   amask  = (const int*)d_in[1];     // [2, 2048] i32
    const float* W      = (const float*)d_in[2];   // [16, 1024, 192] f32
    float* out = (float*)d_out;                    // [2, 2048, 1024] f32
    (void)in_sizes; (void)n_in; (void)out_size;

    __half* hid_t; __half* w_t;
    cudaGetSymbolAddress((void**)&hid_t, g_hid);
    cudaGetSymbolAddress((void**)&w_t, g_wt);

    cudaFuncSetAttribute(qkv_kernel, cudaFuncAttributeMaxDynamicSharedMemorySize, QKV_SMEM_BYTES);
    cudaFuncSetAttribute(flash_kernel, cudaFuncAttributeMaxDynamicSharedMemorySize, FLASH_SMEM_BYTES);

    cvt_kernel<<<1024, 256>>>(hidden, hid_t, BATCH * SEQ * HIDDEN / 4);
    cvtT_kernel<<<dim3(6, 32, 16), 256>>>(W, w_t);
    qkv_kernel<<<dim3(3072 / 128, 4096 / 128), 256, QKV_SMEM_BYTES>>>(hid_t, w_t);
    flash_kernel<<<dim3(SEQ / 64, BATCH * NHEADS), 128, FLASH_SMEM_BYTES>>>(amask, out);
}

// round 11
// speedup vs baseline: 1.0259x; 1.0259x over previous
#include <cuda_runtime.h>
#include <cuda_fp16.h>
#include <cstdint>

#define HIDDEN 1024
#define NHEADS 16
#define HDIM 64
#define BATCH 2
#define SEQ 2048
#define SCALE 0.03125f  /* HIDDEN^-0.5 */
#define L2E 1.4426950408889634f

// scratch (allocation-free rule: __device__ globals) — all fp16
__device__ __half g_q[BATCH * NHEADS * SEQ * HDIM];
__device__ __half g_k[BATCH * NHEADS * SEQ * HDIM];
__device__ __half g_vt[BATCH * NHEADS * HDIM * SEQ];  // V TRANSPOSED: [bh][d][n]
__device__ __half g_hid[BATCH * SEQ * HIDDEN];        // fp16 hidden
__device__ __half g_wt[NHEADS * 192 * HIDDEN];        // fp16 W, TRANSPOSED [h][col][k]

__device__ __forceinline__ unsigned packh2(float a, float b) {
    __half2 h = __floats2half2_rn(a, b);
    return *(unsigned*)&h;
}

// D += A*B, m16n8k16, fp16 inputs, fp32 accumulate
__device__ __forceinline__ void mma_f16(float c[4], const unsigned a[4], const unsigned b[2]) {
    asm volatile(
        "mma.sync.aligned.m16n8k16.row.col.f32.f16.f16.f32 "
        "{%0,%1,%2,%3},{%4,%5,%6,%7},{%8,%9},{%0,%1,%2,%3};\n"
        : "+f"(c[0]), "+f"(c[1]), "+f"(c[2]), "+f"(c[3])
        : "r"(a[0]), "r"(a[1]), "r"(a[2]), "r"(a[3]), "r"(b[0]), "r"(b[1]));
}

__device__ __forceinline__ void ldsm4(unsigned& r0, unsigned& r1, unsigned& r2,
                                      unsigned& r3, unsigned addr) {
    asm volatile("ldmatrix.sync.aligned.m8n8.x4.shared.b16 {%0,%1,%2,%3}, [%4];"
                 : "=r"(r0), "=r"(r1), "=r"(r2), "=r"(r3) : "r"(addr));
}

__device__ __forceinline__ void cp_async16(unsigned dst, const void* src) {
    asm volatile("cp.async.cg.shared.global [%0], [%1], 16;\n" :: "r"(dst), "l"(src));
}
__device__ __forceinline__ void cp_commit() { asm volatile("cp.async.commit_group;\n"); }
__device__ __forceinline__ void cp_wait1() { asm volatile("cp.async.wait_group 1;\n"); }
__device__ __forceinline__ void cp_wait0() { asm volatile("cp.async.wait_group 0;\n"); }

// ---------------------------------------------------------------------------
// Kernel 0a: fp32 -> fp16 (hidden).
// ---------------------------------------------------------------------------
__global__ __launch_bounds__(256) void cvt_kernel(const float* __restrict__ src,
                                                  __half* __restrict__ dst, int n4) {
    int i = blockIdx.x * blockDim.x + threadIdx.x;
    int stride = gridDim.x * blockDim.x;
    for (; i < n4; i += stride) {
        float4 v = ((const float4*)src)[i];
        uint2 u;
        u.x = packh2(v.x, v.y);
        u.y = packh2(v.z, v.w);
        ((uint2*)dst)[i] = u;
    }
}

// ---------------------------------------------------------------------------
// Kernel 0b: fp32 W [h][k][c] -> fp16 TRANSPOSED [h][c][k]. 32x32 tiles.
// ---------------------------------------------------------------------------
__global__ __launch_bounds__(256) void cvtT_kernel(const float* __restrict__ W,
                                                   __half* __restrict__ Wt) {
    __shared__ float t[32][33];
    const int h = blockIdx.z, c0 = blockIdx.x * 32, k0 = blockIdx.y * 32;
    const int tx = threadIdx.x & 31, ty = threadIdx.x >> 5;
    const float* Wh = W + (size_t)h * HIDDEN * 192;
    __half* Wth = Wt + (size_t)h * 192 * HIDDEN;
#pragma unroll
    for (int i = 0; i < 4; i++) {
        int r = ty + 8 * i;
        t[r][tx] = Wh[(size_t)(k0 + r) * 192 + c0 + tx];
    }
    __syncthreads();
#pragma unroll
    for (int i = 0; i < 4; i++) {
        int r = ty + 8 * i;
        Wth[(size_t)(c0 + r) * HIDDEN + k0 + tx] = __float2half(t[tx][r]);
    }
}

// ---------------------------------------------------------------------------
// Kernel 1: fused QKV projection (fp16 m16n8k16, all-LDSM), flattened cols.
// C[4096, 3072]. BM=128, BN=128, BK=64, 256 thr / 8 warps, 3-STAGE cp.async
// pipeline (wait_group 1 keeps one extra tile in flight -> DRAM latency hidden).
// smem: 3 stages x (A 9216 + B 9216) halves = 110592 B; epilogue reuses as
// a 128x136 fp16 C tile for coalesced stores.
// ---------------------------------------------------------------------------
#define QSTR 72
#define QAW 9216
#define QB_BASE 27648
#define QBW 9216
#define QKV_SMEM_BYTES 110592
#define CSTR 136
#define QKT (HIDDEN / 64)

__global__ __launch_bounds__(256, 2) void qkv_kernel(const __half* __restrict__ hidden,
                                                     const __half* __restrict__ Wt) {
    extern __shared__ __half qsh[];
    const unsigned smb = (unsigned)__cvta_generic_to_shared(qsh);

    const int n0  = blockIdx.x * 128;
    const int m0  = blockIdx.y * 128;
    const int tid = threadIdx.x;
    const int wid = tid >> 5, lane = tid & 31;
    const int g   = lane >> 2, tg = lane & 3;
    const int wy  = wid & 3;
    const int wx  = wid >> 2;

    const int rA = (lane & 7) + (((lane >> 3) & 1) << 3);
    const int kA = (lane >> 4) * 8;
    const unsigned lmA = (unsigned)((rA * QSTR + kA) * 2);
    const int rB = (lane & 7) + ((lane >> 4) << 3);
    const int kB = ((lane >> 3) & 1) * 8;
    const unsigned lmB = (unsigned)((rB * QSTR + kB) * 2);

    const int pr = tid >> 1;
    const int pc = (tid & 1) * 32;
    const int gc = n0 + pr;
    const __half* wrow = Wt + (size_t)(gc / 192) * (192 * HIDDEN) + (size_t)(gc % 192) * HIDDEN;
    const __half* arow = hidden + (size_t)(m0 + pr) * HIDDEN;

#define QKV_PREF(st, k0)                                                         \
    {                                                                             \
        _Pragma("unroll")                                                         \
        for (int j = 0; j < 4; j++) {                                             \
            cp_async16(smb + (unsigned)(((st) * QAW + pr * QSTR + pc + 8 * j) * 2), \
                       arow + (k0) + pc + 8 * j);                                 \
            cp_async16(smb + (unsigned)((QB_BASE + (st) * QBW + pr * QSTR + pc + 8 * j) * 2), \
                       wrow + (k0) + pc + 8 * j);                                 \
        }                                                                         \
    }

    QKV_PREF(0, 0);
    cp_commit();
    QKV_PREF(1, 64);
    cp_commit();

    float acc[2][8][4] = {};

    for (int kt = 0; kt < QKT; kt++) {
        const int st = kt % 3;
        if (kt < QKT - 2) cp_wait1(); else cp_wait0();
        __syncthreads();
        if (kt + 2 < QKT) { QKV_PREF((kt + 2) % 3, (kt + 2) * 64); cp_commit(); }

        const unsigned aB = smb + (unsigned)(st * QAW * 2) + lmA;
        const unsigned bB = smb + (unsigned)((QB_BASE + st * QBW) * 2) + lmB;

#pragma unroll
        for (int ks = 0; ks < 4; ks++) {
            const int kk = ks * 16;
            unsigned af[2][4];
#pragma unroll
            for (int mt = 0; mt < 2; mt++)
                ldsm4(af[mt][0], af[mt][1], af[mt][2], af[mt][3],
                      aB + (unsigned)(((wy * 32 + mt * 16) * QSTR + kk) * 2));
#pragma unroll
            for (int ntp = 0; ntp < 4; ntp++) {
                unsigned b0, b1, b2, b3;
                ldsm4(b0, b1, b2, b3, bB + (unsigned)(((wx * 64 + ntp * 16) * QSTR + kk) * 2));
                unsigned bfa[2] = {b0, b1}, bfb[2] = {b2, b3};
#pragma unroll
                for (int mt = 0; mt < 2; mt++) {
                    mma_f16(acc[mt][2 * ntp],     af[mt], bfa);
                    mma_f16(acc[mt][2 * ntp + 1], af[mt], bfb);
                }
            }
        }
    }

    // ---- epilogue: stage C (128x128 fp16) in smem, then coalesced stores ----
    __syncthreads();
#pragma unroll
    for (int mt = 0; mt < 2; mt++) {
        const int row = wy * 32 + mt * 16 + g;
#pragma unroll
        for (int nt = 0; nt < 8; nt++) {
            const int coln = wx * 64 + nt * 8 + 2 * tg;
            *(unsigned*)&qsh[row * CSTR + coln]       = packh2(acc[mt][nt][0], acc[mt][nt][1]);
            *(unsigned*)&qsh[(row + 8) * CSTR + coln] = packh2(acc[mt][nt][2], acc[mt][nt][3]);
        }
    }
    __syncthreads();

    const int b = m0 >> 11;
    const int nbase = m0 & 2047;
#pragma unroll
    for (int gi = 0; gi < 2; gi++) {
        const int gcol = n0 + 64 * gi;
        const int head = gcol / 192;
        const int hc = gcol % 192;
        const int sel = hc >> 6;
        if (sel != 2) {
            __half* dst = (sel == 0) ? g_q : g_k;
            const int r = tid >> 1, ho = (tid & 1) * 32;
            const size_t gbase = (((size_t)(b * NHEADS + head)) * SEQ + nbase + r) * HDIM + ho;
#pragma unroll
            for (int j = 0; j < 4; j++)
                *(uint4*)&dst[gbase + 8 * j] = *(uint4*)&qsh[r * CSTR + 64 * gi + ho + 8 * j];
        } else {
            const int d = tid >> 2, nq = (tid & 3) * 32;
            const size_t gbase = ((size_t)(b * NHEADS + head) * HDIM + d) * SEQ + nbase + nq;
#pragma unroll
            for (int j = 0; j < 4; j++) {
                __half tmp[8];
#pragma unroll
                for (int u = 0; u < 8; u++)
                    tmp[u] = qsh[(nq + 8 * j + u) * CSTR + 64 * gi + d];
                *(uint4*)&g_vt[gbase + 8 * j] = *(uint4*)tmp;
            }
        }
    }
}

// ---------------------------------------------------------------------------
// Kernel 2: flash attention (fp16 m16n8k16). BQ=128, 256 thr / 8 warps,
// 2 blocks/SM. Staging buffers hold 128 keys, processed as 2x64-key halves:
// barrier/wait frequency halves vs R8 (16 outer iters instead of 32).
// smem halves: K[2][128*72] @0, Vt[2][64*136] @18432; flags int[2][128] @71680B
// ---------------------------------------------------------------------------
#define KSTRh 72
#define VSTRh 136
#define VBASEh 18432
#define FLIi 17920          /* int index of flags (byte 71680) */
#define FLASH_SMEM_BYTES 72704

__global__ __launch_bounds__(256, 2) void flash_kernel(const int* __restrict__ mask,
                                                       float* __restrict__ out) {
    extern __shared__ __half smh[];
    int* smi = (int*)smh;
    const unsigned smbase = (unsigned)__cvta_generic_to_shared(smh);

    const int bh = blockIdx.y, b = bh >> 4, h = bh & 15;
    const int q0 = blockIdx.x * 128;
    const int tid = threadIdx.x, wid = tid >> 5, lane = tid & 31;
    const int g = lane >> 2, tg = lane & 3;
    const int row0 = wid * 16 + g, row1 = row0 + 8;

    const __half* Qg  = g_q + (size_t)bh * SEQ * HDIM;
    const __half* Kg  = g_k + (size_t)bh * SEQ * HDIM;
    const __half* Vtg = g_vt + (size_t)bh * HDIM * SEQ;
    const int* maskb = mask + b * SEQ;

    const int rA = (lane & 7) + (((lane >> 3) & 1) << 3);
    const int kA = (lane >> 4) * 8;
    const unsigned lmA = (unsigned)((rA * KSTRh + kA) * 2);
    const int rB = (lane & 7) + ((lane >> 4) << 3);
    const int kB = ((lane >> 3) & 1) * 8;
    const unsigned lmBk = (unsigned)((rB * KSTRh + kB) * 2);
    const unsigned lmBv = (unsigned)((rB * VSTRh + kB) * 2);

    // ---- stage Q (x SCALE) as fp16 into K-buffer0 area, pull A-frags ----
    {
        const __half2 hs = __float2half2_rn(SCALE);
        const int lr = tid >> 1;
        const int lgp = (tid & 1) * 8;
        const uint2* qrow = (const uint2*)&Qg[(size_t)(q0 + lr) * HDIM];
#pragma unroll
        for (int j = 0; j < 8; j++) {
            uint2 u = qrow[lgp + j];
            __half2* hp = (__half2*)&u;
            hp[0] = __hmul2(hp[0], hs);
            hp[1] = __hmul2(hp[1], hs);
            *(uint2*)&smh[lr * KSTRh + (lgp + j) * 4] = u;
        }
    }
    __syncthreads();
    unsigned qa[4][4];
#pragma unroll
    for (int kc = 0; kc < 4; kc++)
        ldsm4(qa[kc][0], qa[kc][1], qa[kc][2], qa[kc][3],
              smbase + (unsigned)((wid * 16 * KSTRh + kc * 16) * 2) + lmA);
    __syncthreads();

    // prefetch: K 128 keys x 64 halves (4 chunks/thr); Vt 64 d x 128 keys (4/thr)
    const int kr = tid >> 1;
    const int kc2 = (tid & 1) * 32;
    const int vr = tid >> 2;
    const int vc = (tid & 3) * 32;
#define PREFETCH(buf, j0)                                                         \
    {                                                                             \
        _Pragma("unroll")                                                         \
        for (int j = 0; j < 4; j++) {                                             \
            cp_async16(smbase + (unsigned)(((buf) * 9216 + kr * KSTRh + kc2 + 8 * j) * 2), \
                       &Kg[(size_t)((j0) + kr) * HDIM + kc2 + 8 * j]);            \
            cp_async16(smbase + (unsigned)((VBASEh + (buf) * 8704 + vr * VSTRh + vc + 8 * j) * 2), \
                       &Vtg[(size_t)vr * SEQ + (j0) + vc + 8 * j]);               \
        }                                                                         \
        if (tid < 32)                                                             \
            cp_async16(smbase + (unsigned)(71680 + (buf) * 512 + tid * 16),       \
                       &maskb[(j0) + tid * 4]);                                   \
    }

    PREFETCH(0, 0);
    cp_commit();

    float l0r = 0.f, l1r = 0.f;
    float o[8][4] = {};
    float s[8][4];

    for (int it = 0; it < 16; ++it) {
        const int c = it & 1;

        cp_wait0();
        __syncthreads();
        if (it + 1 < 16) { PREFETCH(c ^ 1, (it + 1) * 128); cp_commit(); }

#pragma unroll
        for (int hh = 0; hh < 2; hh++) {
            const unsigned kbB = smbase + (unsigned)((c * 9216 + hh * 64 * KSTRh) * 2) + lmBk;
            const unsigned vbB = smbase + (unsigned)((VBASEh + c * 8704) * 2) + lmBv
                               + (unsigned)(hh * 64 * 2);

            // ---- S = Q K^T ----
#pragma unroll
            for (int nt = 0; nt < 8; nt++) { s[nt][0] = 0.f; s[nt][1] = 0.f; s[nt][2] = 0.f; s[nt][3] = 0.f; }
#pragma unroll
            for (int kc = 0; kc < 4; kc++) {
                const int kk = kc * 16;
#pragma unroll
                for (int ntp = 0; ntp < 4; ntp++) {
                    unsigned b0, b1, b2, b3;
                    ldsm4(b0, b1, b2, b3, kbB + (unsigned)((ntp * 16 * KSTRh + kk) * 2));
                    unsigned bfa[2] = {b0, b1}, bfb[2] = {b2, b3};
                    mma_f16(s[2 * ntp],     qa[kc], bfa);
                    mma_f16(s[2 * ntp + 1], qa[kc], bfb);
                }
            }

            // ---- mask + P = 2^(s*log2e) via f16x2 MUFU; fp32 row sums ----
            unsigned p01[8], p23[8];
            float ps0 = 0.f, ps1 = 0.f;
#pragma unroll
            for (int nt = 0; nt < 8; nt++) {
                const int cb = nt * 8 + 2 * tg;
                if (smi[FLIi + c * 128 + hh * 64 + cb] == 0)     { s[nt][0] = -1e4f; s[nt][2] = -1e4f; }
                if (smi[FLIi + c * 128 + hh * 64 + cb + 1] == 0) { s[nt][1] = -1e4f; s[nt][3] = -1e4f; }
                unsigned a01 = packh2(s[nt][0] * L2E, s[nt][1] * L2E);
                unsigned a23 = packh2(s[nt][2] * L2E, s[nt][3] * L2E);
                asm("ex2.approx.f16x2 %0, %0;" : "+r"(a01));
                asm("ex2.approx.f16x2 %0, %0;" : "+r"(a23));
                p01[nt] = a01; p23[nt] = a23;
                float2 f0 = __half22float2(*(__half2*)&a01);
                float2 f1 = __half22float2(*(__half2*)&a23);
                ps0 += f0.x + f0.y;
                ps1 += f1.x + f1.y;
            }
            ps0 += __shfl_xor_sync(0xffffffffu, ps0, 1);
            ps0 += __shfl_xor_sync(0xffffffffu, ps0, 2);
            ps1 += __shfl_xor_sync(0xffffffffu, ps1, 1);
            ps1 += __shfl_xor_sync(0xffffffffu, ps1, 2);
            l0r += ps0;
            l1r += ps1;

            // ---- O += P V ----
#pragma unroll
            for (int kc = 0; kc < 4; kc++) {
                unsigned ap[4];
                ap[0] = p01[2 * kc];     ap[1] = p23[2 * kc];
                ap[2] = p01[2 * kc + 1]; ap[3] = p23[2 * kc + 1];
#pragma unroll
                for (int ntp = 0; ntp < 4; ntp++) {
                    unsigned b0, b1, b2, b3;
                    ldsm4(b0, b1, b2, b3, vbB + (unsigned)((ntp * 16 * VSTRh + kc * 16) * 2));
                    unsigned bfa[2] = {b0, b1}, bfb[2] = {b2, b3};
                    mma_f16(o[2 * ntp],     ap, bfa);
                    mma_f16(o[2 * ntp + 1], ap, bfb);
                }
            }
        }
    }

    const float inv0 = 1.f / l0r, inv1 = 1.f / l1r;
#pragma unroll
    for (int nt = 0; nt < 8; nt++) {
        const int col = h * HDIM + nt * 8 + 2 * tg;
        const size_t o0 = ((size_t)(b * SEQ + q0 + row0)) * HIDDEN + col;
        const size_t o1 = ((size_t)(b * SEQ + q0 + row1)) * HIDDEN + col;
        *(float2*)&out[o0] = make_float2(o[nt][0] * inv0, o[nt][1] * inv0);
        *(float2*)&out[o1] = make_float2(o[nt][2] * inv1, o[nt][3] * inv1);
    }
}

// ---------------------------------------------------------------------------
extern "C" void kernel_launch(void* const* d_in, const int* in_sizes, int n_in,
                              void* d_out, int out_size) {
    const float* hidden = (const float*)d_in[0];   // [2, 2048, 1024] f32
    const int*   amask  = (const int*)d_in[1];     // [2, 2048] i32
    const float* W      = (const float*)d_in[2];   // [16, 1024, 192] f32
    float* out = (float*)d_out;                    // [2, 2048, 1024] f32
    (void)in_sizes; (void)n_in; (void)out_size;

    __half* hid_t; __half* w_t;
    cudaGetSymbolAddress((void**)&hid_t, g_hid);
    cudaGetSymbolAddress((void**)&w_t, g_wt);

    cudaFuncSetAttribute(qkv_kernel, cudaFuncAttributeMaxDynamicSharedMemorySize, QKV_SMEM_BYTES);
    cudaFuncSetAttribute(flash_kernel, cudaFuncAttributeMaxDynamicSharedMemorySize, FLASH_SMEM_BYTES);

    cvt_kernel<<<1024, 256>>>(hidden, hid_t, BATCH * SEQ * HIDDEN / 4);
    cvtT_kernel<<<dim3(6, 32, 16), 256>>>(W, w_t);
    qkv_kernel<<<dim3(3072 / 128, 4096 / 128), 256, QKV_SMEM_BYTES>>>(hid_t, w_t);
    flash_kernel<<<dim3(SEQ / 128, BATCH * NHEADS), 256, FLASH_SMEM_BYTES>>>(amask, out);
}

// round 13
// speedup vs baseline: 1.1201x; 1.0918x over previous
#include <cuda_runtime.h>
#include <cuda_fp16.h>
#include <cstdint>

#define HIDDEN 1024
#define NHEADS 16
#define HDIM 64
#define BATCH 2
#define SEQ 2048
#define SCALE 0.03125f  /* HIDDEN^-0.5 */
#define L2E 1.4426950408889634f

// scratch (allocation-free rule: __device__ globals) — all fp16
__device__ __half g_q[BATCH * NHEADS * SEQ * HDIM];
__device__ __half g_k[BATCH * NHEADS * SEQ * HDIM];
__device__ __half g_vt[BATCH * NHEADS * HDIM * SEQ];  // V TRANSPOSED: [bh][d][n]
__device__ __half g_hid[BATCH * SEQ * HIDDEN];        // fp16 hidden
__device__ __half g_wt[NHEADS * 192 * HIDDEN];        // fp16 W, TRANSPOSED [h][col][k]

__device__ __forceinline__ unsigned packh2(float a, float b) {
    __half2 h = __floats2half2_rn(a, b);
    return *(unsigned*)&h;
}

// D += A*B, m16n8k16, fp16 in, fp32 acc (PV phase)
__device__ __forceinline__ void mma_f16(float c[4], const unsigned a[4], const unsigned b[2]) {
    asm volatile(
        "mma.sync.aligned.m16n8k16.row.col.f32.f16.f16.f32 "
        "{%0,%1,%2,%3},{%4,%5,%6,%7},{%8,%9},{%0,%1,%2,%3};\n"
        : "+f"(c[0]), "+f"(c[1]), "+f"(c[2]), "+f"(c[3])
        : "r"(a[0]), "r"(a[1]), "r"(a[2]), "r"(a[3]), "r"(b[0]), "r"(b[1]));
}

// D += A*B, m16n8k16, fp16 in, fp16 acc (S phase: d0 = rows g cols {2tg,2tg+1})
__device__ __forceinline__ void mma_f16acc(unsigned c[2], const unsigned a[4], const unsigned b[2]) {
    asm volatile(
        "mma.sync.aligned.m16n8k16.row.col.f16.f16.f16.f16 "
        "{%0,%1},{%2,%3,%4,%5},{%6,%7},{%0,%1};\n"
        : "+r"(c[0]), "+r"(c[1])
        : "r"(a[0]), "r"(a[1]), "r"(a[2]), "r"(a[3]), "r"(b[0]), "r"(b[1]));
}

__device__ __forceinline__ void ldsm4(unsigned& r0, unsigned& r1, unsigned& r2,
                                      unsigned& r3, unsigned addr) {
    asm volatile("ldmatrix.sync.aligned.m8n8.x4.shared.b16 {%0,%1,%2,%3}, [%4];"
                 : "=r"(r0), "=r"(r1), "=r"(r2), "=r"(r3) : "r"(addr));
}

__device__ __forceinline__ void cp_async16(unsigned dst, const void* src) {
    asm volatile("cp.async.cg.shared.global [%0], [%1], 16;\n" :: "r"(dst), "l"(src));
}
__device__ __forceinline__ void cp_commit() { asm volatile("cp.async.commit_group;\n"); }
__device__ __forceinline__ void cp_wait1() { asm volatile("cp.async.wait_group 1;\n"); }
__device__ __forceinline__ void cp_wait0() { asm volatile("cp.async.wait_group 0;\n"); }

// ---------------------------------------------------------------------------
// Kernel 0a: fp32 -> fp16 (hidden).
// ---------------------------------------------------------------------------
__global__ __launch_bounds__(256) void cvt_kernel(const float* __restrict__ src,
                                                  __half* __restrict__ dst, int n4) {
    int i = blockIdx.x * blockDim.x + threadIdx.x;
    int stride = gridDim.x * blockDim.x;
    for (; i < n4; i += stride) {
        float4 v = ((const float4*)src)[i];
        uint2 u;
        u.x = packh2(v.x, v.y);
        u.y = packh2(v.z, v.w);
        ((uint2*)dst)[i] = u;
    }
}

// ---------------------------------------------------------------------------
// Kernel 0b: fp32 W [h][k][c] -> fp16 TRANSPOSED [h][c][k]. 32x32 tiles.
// ---------------------------------------------------------------------------
__global__ __launch_bounds__(256) void cvtT_kernel(const float* __restrict__ W,
                                                   __half* __restrict__ Wt) {
    __shared__ float t[32][33];
    const int h = blockIdx.z, c0 = blockIdx.x * 32, k0 = blockIdx.y * 32;
    const int tx = threadIdx.x & 31, ty = threadIdx.x >> 5;
    const float* Wh = W + (size_t)h * HIDDEN * 192;
    __half* Wth = Wt + (size_t)h * 192 * HIDDEN;
#pragma unroll
    for (int i = 0; i < 4; i++) {
        int r = ty + 8 * i;
        t[r][tx] = Wh[(size_t)(k0 + r) * 192 + c0 + tx];
    }
    __syncthreads();
#pragma unroll
    for (int i = 0; i < 4; i++) {
        int r = ty + 8 * i;
        Wth[(size_t)(c0 + r) * HIDDEN + k0 + tx] = __float2half(t[tx][r]);
    }
}

// ---------------------------------------------------------------------------
// Kernel 1: fused QKV projection (fp16 m16n8k16, all-LDSM), flattened cols.
// C[4096, 3072]. BM=128, BN=128, BK=64, 256 thr / 8 warps, 2-stage cp.async.
// Staged smem epilogue -> coalesced 16B stores (incl. Vt transpose).
// smem halves: A[2][128*72] @0, B[2][128*72] @18432 = 36864 (73728 B);
// epilogue reuses as a 128x136 fp16 C tile.
// ---------------------------------------------------------------------------
#define QSTR 72
#define QAW 9216
#define QB_BASE 18432
#define QBW 9216
#define QKV_SMEM_BYTES 73728
#define CSTR 136

__global__ __launch_bounds__(256, 2) void qkv_kernel(const __half* __restrict__ hidden,
                                                     const __half* __restrict__ Wt) {
    extern __shared__ __half qsh[];
    const unsigned smb = (unsigned)__cvta_generic_to_shared(qsh);

    const int n0  = blockIdx.x * 128;
    const int m0  = blockIdx.y * 128;
    const int tid = threadIdx.x;
    const int wid = tid >> 5, lane = tid & 31;
    const int g   = lane >> 2, tg = lane & 3;
    const int wy  = wid & 3;
    const int wx  = wid >> 2;

    const int rA = (lane & 7) + (((lane >> 3) & 1) << 3);
    const int kA = (lane >> 4) * 8;
    const unsigned lmA = (unsigned)((rA * QSTR + kA) * 2);
    const int rB = (lane & 7) + ((lane >> 4) << 3);
    const int kB = ((lane >> 3) & 1) * 8;
    const unsigned lmB = (unsigned)((rB * QSTR + kB) * 2);

    const int pr = tid >> 1;
    const int pc = (tid & 1) * 32;
    const int gc = n0 + pr;
    const __half* wrow = Wt + (size_t)(gc / 192) * (192 * HIDDEN) + (size_t)(gc % 192) * HIDDEN;
    const __half* arow = hidden + (size_t)(m0 + pr) * HIDDEN;

#define QKV_PREF(buf, k0)                                                        \
    {                                                                             \
        _Pragma("unroll")                                                         \
        for (int j = 0; j < 4; j++) {                                             \
            cp_async16(smb + (unsigned)(((buf) * QAW + pr * QSTR + pc + 8 * j) * 2), \
                       arow + (k0) + pc + 8 * j);                                 \
            cp_async16(smb + (unsigned)((QB_BASE + (buf) * QBW + pr * QSTR + pc + 8 * j) * 2), \
                       wrow + (k0) + pc + 8 * j);                                 \
        }                                                                         \
    }

    QKV_PREF(0, 0);
    cp_commit();

    float acc[2][8][4] = {};

    for (int kt = 0; kt < HIDDEN / 64; kt++) {
        const int c = kt & 1;
        cp_wait0();
        __syncthreads();
        if (kt + 1 < HIDDEN / 64) { QKV_PREF(c ^ 1, (kt + 1) * 64); cp_commit(); }

        const unsigned aB = smb + (unsigned)(c * QAW * 2) + lmA;
        const unsigned bB = smb + (unsigned)((QB_BASE + c * QBW) * 2) + lmB;

#pragma unroll
        for (int ks = 0; ks < 4; ks++) {
            const int kk = ks * 16;
            unsigned af[2][4];
#pragma unroll
            for (int mt = 0; mt < 2; mt++)
                ldsm4(af[mt][0], af[mt][1], af[mt][2], af[mt][3],
                      aB + (unsigned)(((wy * 32 + mt * 16) * QSTR + kk) * 2));
#pragma unroll
            for (int ntp = 0; ntp < 4; ntp++) {
                unsigned b0, b1, b2, b3;
                ldsm4(b0, b1, b2, b3, bB + (unsigned)(((wx * 64 + ntp * 16) * QSTR + kk) * 2));
                unsigned bfa[2] = {b0, b1}, bfb[2] = {b2, b3};
#pragma unroll
                for (int mt = 0; mt < 2; mt++) {
                    mma_f16(acc[mt][2 * ntp],     af[mt], bfa);
                    mma_f16(acc[mt][2 * ntp + 1], af[mt], bfb);
                }
            }
        }
    }

    // ---- epilogue: stage C (128x128 fp16) in smem, then coalesced stores ----
    __syncthreads();
#pragma unroll
    for (int mt = 0; mt < 2; mt++) {
        const int row = wy * 32 + mt * 16 + g;
#pragma unroll
        for (int nt = 0; nt < 8; nt++) {
            const int coln = wx * 64 + nt * 8 + 2 * tg;
            *(unsigned*)&qsh[row * CSTR + coln]       = packh2(acc[mt][nt][0], acc[mt][nt][1]);
            *(unsigned*)&qsh[(row + 8) * CSTR + coln] = packh2(acc[mt][nt][2], acc[mt][nt][3]);
        }
    }
    __syncthreads();

    const int b = m0 >> 11;
    const int nbase = m0 & 2047;
#pragma unroll
    for (int gi = 0; gi < 2; gi++) {
        const int gcol = n0 + 64 * gi;
        const int head = gcol / 192;
        const int hc = gcol % 192;
        const int sel = hc >> 6;
        if (sel != 2) {
            __half* dst = (sel == 0) ? g_q : g_k;
            const int r = tid >> 1, ho = (tid & 1) * 32;
            const size_t gbase = (((size_t)(b * NHEADS + head)) * SEQ + nbase + r) * HDIM + ho;
#pragma unroll
            for (int j = 0; j < 4; j++)
                *(uint4*)&dst[gbase + 8 * j] = *(uint4*)&qsh[r * CSTR + 64 * gi + ho + 8 * j];
        } else {
            const int d = tid >> 2, nq = (tid & 3) * 32;
            const size_t gbase = ((size_t)(b * NHEADS + head) * HDIM + d) * SEQ + nbase + nq;
#pragma unroll
            for (int j = 0; j < 4; j++) {
                __half tmp[8];
#pragma unroll
                for (int u = 0; u < 8; u++)
                    tmp[u] = qsh[(nq + 8 * j + u) * CSTR + 64 * gi + d];
                *(uint4*)&g_vt[gbase + 8 * j] = *(uint4*)tmp;
            }
        }
    }
}

// ---------------------------------------------------------------------------
// Kernel 2: flash attention. BQ=128, BKV=64, 256 thr / 8 warps, 2 blocks/SM.
// S phase: fp16-accumulate HMMA (full-rate path; accumulators arrive packed
// in the PV A-fragment layout). Softmax: ex2.approx.f16x2; masking by
// half2 {0,1} flag multiply AFTER exp (exact zeros). PV: fp32 accumulate.
// smem halves: K[2][64*72] @0, Vt[2][64*72] @9216; flags(int)[2][64] @36864B.
// ---------------------------------------------------------------------------
#define FSTR 72
#define FVBASE 9216
#define FLI 9216          /* int index of flags (byte 36864) */
#define FLASH_SMEM_BYTES 37376

__global__ __launch_bounds__(256, 2) void flash_kernel(const int* __restrict__ mask,
                                                       float* __restrict__ out) {
    extern __shared__ __half smh[];
    int* smi = (int*)smh;
    const unsigned smbase = (unsigned)__cvta_generic_to_shared(smh);

    const int bh = blockIdx.y, b = bh >> 4, h = bh & 15;
    const int q0 = blockIdx.x * 128;
    const int tid = threadIdx.x, wid = tid >> 5, lane = tid & 31;
    const int g = lane >> 2, tg = lane & 3;
    const int row0 = wid * 16 + g, row1 = row0 + 8;

    const __half* Qg  = g_q + (size_t)bh * SEQ * HDIM;
    const __half* Kg  = g_k + (size_t)bh * SEQ * HDIM;
    const __half* Vtg = g_vt + (size_t)bh * HDIM * SEQ;
    const int* maskb = mask + b * SEQ;

    const int rA = (lane & 7) + (((lane >> 3) & 1) << 3);
    const int kA = (lane >> 4) * 8;
    const unsigned lmA = (unsigned)((rA * FSTR + kA) * 2);
    const int rB = (lane & 7) + ((lane >> 4) << 3);
    const int kB = ((lane >> 3) & 1) * 8;
    const unsigned lmB = (unsigned)((rB * FSTR + kB) * 2);

    // ---- stage Q (x SCALE) as fp16 into smem, pull A-frags, free buffer ----
    {
        const __half2 hs = __float2half2_rn(SCALE);
        const int lr = tid >> 1;
        const int lgp = (tid & 1) * 8;
        const uint2* qrow = (const uint2*)&Qg[(size_t)(q0 + lr) * HDIM];
#pragma unroll
        for (int j = 0; j < 8; j++) {
            uint2 u = qrow[lgp + j];
            __half2* hp = (__half2*)&u;
            hp[0] = __hmul2(hp[0], hs);
            hp[1] = __hmul2(hp[1], hs);
            *(uint2*)&smh[lr * FSTR + (lgp + j) * 4] = u;
        }
    }
    __syncthreads();
    unsigned qa[4][4];
#pragma unroll
    for (int kc = 0; kc < 4; kc++)
        ldsm4(qa[kc][0], qa[kc][1], qa[kc][2], qa[kc][3],
              smbase + (unsigned)((wid * 16 * FSTR + kc * 16) * 2) + lmA);
    __syncthreads();

    const int kr = tid >> 2;
    const int kc4 = (tid & 3) * 16;
#define PREFETCH(buf, j0)                                                         \
    {                                                                             \
        _Pragma("unroll")                                                         \
        for (int j = 0; j < 2; j++) {                                             \
            cp_async16(smbase + (unsigned)(((buf) * 4608 + kr * FSTR + kc4 + 8 * j) * 2), \
                       &Kg[(size_t)((j0) + kr) * HDIM + kc4 + 8 * j]);            \
            cp_async16(smbase + (unsigned)((FVBASE + (buf) * 4608 + kr * FSTR + kc4 + 8 * j) * 2), \
                       &Vtg[(size_t)kr * SEQ + (j0) + kc4 + 8 * j]);              \
        }                                                                         \
        if (tid < 16)                                                             \
            cp_async16(smbase + (unsigned)(36864 + (buf) * 256 + tid * 16),       \
                       &maskb[(j0) + tid * 4]);                                   \
    }

    PREFETCH(0, 0);
    cp_commit();

    float l0r = 0.f, l1r = 0.f;
    float o[8][4] = {};

    const __half2 l2e2 = __float2half2_rn(L2E);

    for (int it = 0; it < 32; ++it) {
        const int c = it & 1;
        const unsigned kbB = smbase + (unsigned)(c * 4608 * 2) + lmB;
        const unsigned vbB = smbase + (unsigned)((FVBASE + c * 4608) * 2) + lmB;

        cp_wait0();
        __syncthreads();
        if (it + 1 < 32) { PREFETCH(c ^ 1, (it + 1) * 64); cp_commit(); }

        // ---- S = Q K^T, fp16 accumulate (packed in A-frag layout) ----
        unsigned sd[8][2];
#pragma unroll
        for (int nt = 0; nt < 8; nt++) { sd[nt][0] = 0u; sd[nt][1] = 0u; }
#pragma unroll
        for (int kc = 0; kc < 4; kc++) {
            const int kk = kc * 16;
#pragma unroll
            for (int ntp = 0; ntp < 4; ntp++) {
                unsigned b0, b1, b2, b3;
                ldsm4(b0, b1, b2, b3, kbB + (unsigned)((ntp * 16 * FSTR + kk) * 2));
                unsigned bfa[2] = {b0, b1}, bfb[2] = {b2, b3};
                mma_f16acc(sd[2 * ntp],     qa[kc], bfa);
                mma_f16acc(sd[2 * ntp + 1], qa[kc], bfb);
            }
        }

        // ---- P = 2^(s*log2e) (f16x2 MUFU); mask by {0,1} flag multiply ----
        unsigned p01[8], p23[8];
        float ps0 = 0.f, ps1 = 0.f;
#pragma unroll
        for (int nt = 0; nt < 8; nt++) {
            const int cb = nt * 8 + 2 * tg;
            const unsigned flu = (smi[FLI + c * 64 + cb] ? 0x3C00u : 0u)
                               | (smi[FLI + c * 64 + cb + 1] ? 0x3C000000u : 0u);
            const __half2 flh = *(const __half2*)&flu;
            __half2 e0 = __hmul2(*(__half2*)&sd[nt][0], l2e2);
            __half2 e1 = __hmul2(*(__half2*)&sd[nt][1], l2e2);
            unsigned u0 = *(unsigned*)&e0, u1 = *(unsigned*)&e1;
            asm("ex2.approx.f16x2 %0, %0;" : "+r"(u0));
            asm("ex2.approx.f16x2 %0, %0;" : "+r"(u1));
            __half2 h0 = __hmul2(*(__half2*)&u0, flh);
            __half2 h1 = __hmul2(*(__half2*)&u1, flh);
            p01[nt] = *(unsigned*)&h0;
            p23[nt] = *(unsigned*)&h1;
            float2 f0 = __half22float2(h0);
            float2 f1 = __half22float2(h1);
            ps0 += f0.x + f0.y;
            ps1 += f1.x + f1.y;
        }
        ps0 += __shfl_xor_sync(0xffffffffu, ps0, 1);
        ps0 += __shfl_xor_sync(0xffffffffu, ps0, 2);
        ps1 += __shfl_xor_sync(0xffffffffu, ps1, 1);
        ps1 += __shfl_xor_sync(0xffffffffu, ps1, 2);
        l0r += ps0;
        l1r += ps1;

        // ---- O += P V (fp32 accumulate): P A-frags are the ex2 outputs ----
#pragma unroll
        for (int kc = 0; kc < 4; kc++) {
            unsigned ap[4];
            ap[0] = p01[2 * kc];     ap[1] = p23[2 * kc];
            ap[2] = p01[2 * kc + 1]; ap[3] = p23[2 * kc + 1];
#pragma unroll
            for (int ntp = 0; ntp < 4; ntp++) {
                unsigned b0, b1, b2, b3;
                ldsm4(b0, b1, b2, b3, vbB + (unsigned)((ntp * 16 * FSTR + kc * 16) * 2));
                unsigned bfa[2] = {b0, b1}, bfb[2] = {b2, b3};
                mma_f16(o[2 * ntp],     ap, bfa);
                mma_f16(o[2 * ntp + 1], ap, bfb);
            }
        }
    }

    const float inv0 = 1.f / l0r, inv1 = 1.f / l1r;
#pragma unroll
    for (int nt = 0; nt < 8; nt++) {
        const int col = h * HDIM + nt * 8 + 2 * tg;
        const size_t o0 = ((size_t)(b * SEQ + q0 + row0)) * HIDDEN + col;
        const size_t o1 = ((size_t)(b * SEQ + q0 + row1)) * HIDDEN + col;
        *(float2*)&out[o0] = make_float2(o[nt][0] * inv0, o[nt][1] * inv0);
        *(float2*)&out[o1] = make_float2(o[nt][2] * inv1, o[nt][3] * inv1);
    }
}

// ---------------------------------------------------------------------------
extern "C" void kernel_launch(void* const* d_in, const int* in_sizes, int n_in,
                              void* d_out, int out_size) {
    const float* hidden = (const float*)d_in[0];   // [2, 2048, 1024] f32
    const int*   amask  = (const int*)d_in[1];     // [2, 2048] i32
    const float* W      = (const float*)d_in[2];   // [16, 1024, 192] f32
    float* out = (float*)d_out;                    // [2, 2048, 1024] f32
    (void)in_sizes; (void)n_in; (void)out_size;

    __half* hid_t; __half* w_t;
    cudaGetSymbolAddress((void**)&hid_t, g_hid);
    cudaGetSymbolAddress((void**)&w_t, g_wt);

    cudaFuncSetAttribute(qkv_kernel, cudaFuncAttributeMaxDynamicSharedMemorySize, QKV_SMEM_BYTES);
    cudaFuncSetAttribute(flash_kernel, cudaFuncAttributeMaxDynamicSharedMemorySize, FLASH_SMEM_BYTES);

    cvt_kernel<<<1024, 256>>>(hidden, hid_t, BATCH * SEQ * HIDDEN / 4);
    cvtT_kernel<<<dim3(6, 32, 16), 256>>>(W, w_t);
    qkv_kernel<<<dim3(3072 / 128, 4096 / 128), 256, QKV_SMEM_BYTES>>>(hid_t, w_t);
    flash_kernel<<<dim3(SEQ / 128, BATCH * NHEADS), 256, FLASH_SMEM_BYTES>>>(amask, out);
}